// round 16
// baseline (speedup 1.0000x reference)
#include <cuda_runtime.h>
#include <math.h>
#include <float.h>
#include <stdint.h>

#define BATCH   16384
#define IN_DIM  362
#define HID     256
#define NSTY    60
#define NOUT    49710
#define D2      724     // 2*IN_DIM

// ---------------- scratch ----------------
__device__ float  g_emb[3][BATCH][HID];
__device__ int    g_idx[2][BATCH];
__device__ float  g_sscore[2][NSTY];
__device__ float  g_cnorm[2][NSTY];
__device__ double g_acc[4];               // 0:loss1  1:sum m^2  2:cross  3:auc
__device__ double g_K[2][4096];
__device__ double g_G[2][4096];

// ---------------- helpers ----------------
__device__ __forceinline__ float sigmoid_f(float x) { return 1.0f / (1.0f + expf(-x)); }
__device__ __forceinline__ float softplus_f(float y) {
    return fmaxf(y, 0.0f) + log1pf(expf(-fabsf(y)));
}
__device__ __forceinline__ uint32_t f2tf32(float x) {
    uint32_t r;
    asm("cvt.rna.tf32.f32 %0, %1;" : "=r"(r) : "f"(x));
    return r;
}
__device__ __forceinline__ void mma_tf32(float* d, const uint32_t* a, const uint32_t* b) {
    asm volatile(
        "mma.sync.aligned.m16n8k8.row.col.f32.tf32.tf32.f32 "
        "{%0,%1,%2,%3}, {%4,%5,%6,%7}, {%8,%9}, {%0,%1,%2,%3};"
        : "+f"(d[0]), "+f"(d[1]), "+f"(d[2]), "+f"(d[3])
        : "r"(a[0]), "r"(a[1]), "r"(a[2]), "r"(a[3]), "r"(b[0]), "r"(b[1]));
}
__device__ __forceinline__ float2 loadF2(const float* fa, const float* fb,
                                         int rowg, int d) {
    if (d < IN_DIM) return *(const float2*)&fa[(size_t)rowg * IN_DIM + d];
    if (d < D2)     return *(const float2*)&fb[(size_t)rowg * IN_DIM + d - IN_DIM];
    return make_float2(0.0f, 0.0f);
}

// ---------------- K0: zero ----------------
__global__ void k_zero() {
    int gid = blockIdx.x * 256 + threadIdx.x;      // 64 x 256
    if (gid < 8192)      ((double*)g_K)[gid] = 0.0;
    else                 ((double*)g_G)[gid - 8192] = 0.0;
    if (gid < 4) g_acc[gid] = 0.0;
}

// ================= device bodies (uniform per block) =================

// ---- style: score table + column norms (s, z) ----
__device__ void dev_style(uint32_t* sm, int s, int z,
                          const float* Pm, const float* Nm,
                          const float* Wt, const float* bt,
                          const float* Wb, const float* bb) {
    float* pc  = (float*)sm;            // [724]
    float* red = pc + D2;               // [256]
    const float* M = z ? Nm : Pm;
    int tid = threadIdx.x;
    for (int d = tid; d < D2; d += 256)
        pc[d] = fmaxf(M[d * NSTY + s], 0.0f);
    __syncthreads();

    float t = bt[tid], b = bb[tid];
    for (int d = 0; d < IN_DIM; d++) {
        t = fmaf(pc[d],          Wt[d * HID + tid], t);
        b = fmaf(pc[IN_DIM + d], Wb[d * HID + tid], b);
    }
    float v = sigmoid_f(t) * sigmoid_f(b);
    red[tid] = v; __syncthreads();
    for (int off = 128; off > 0; off >>= 1) {
        if (tid < off) red[tid] += red[tid + off];
        __syncthreads();
    }
    if (tid == 0) g_sscore[z][s] = red[0];

    float n = 0.0f;
    for (int d = tid; d < D2; d += 256) n = fmaf(pc[d], pc[d], n);
    __syncthreads();
    red[tid] = n; __syncthreads();
    for (int off = 128; off > 0; off >>= 1) {
        if (tid < off) red[tid] += red[tid + off];
        __syncthreads();
    }
    if (tid == 0) g_cnorm[z][s] = red[0];
}

// ---- hgram: K = relu(H) relu(H)^T, grid-strided chunks ----
#define HG_CHUNKS 777
#define HG_BLOCKS 148
__device__ void dev_hgram(uint32_t* sm, int blk, int z,
                          const float* H1, const float* H2) {
    uint32_t (*Hh)[68] = (uint32_t (*)[68])sm;
    uint32_t (*Hl)[68] = (uint32_t (*)[68])(sm + 64 * 68);
    const float* H = z ? H2 : H1;
    int tid = threadIdx.x;
    int lane = tid & 31, w = tid >> 5;
    int r = lane >> 2, tg = lane & 3;
    int m0w = (w >> 2) * 32;
    int n0w = (w & 3) * 16;

    float acc[2][2][4];
    #pragma unroll
    for (int mi = 0; mi < 2; mi++)
        #pragma unroll
        for (int ni = 0; ni < 2; ni++)
            #pragma unroll
            for (int q = 0; q < 4; q++) acc[mi][ni][q] = 0.0f;

    for (int c = blk; c < HG_CHUNKS; c += HG_BLOCKS) {
        int o0 = c * 64;
        #pragma unroll
        for (int i = 0; i < 16; i++) {
            int idx = tid + i * 256;
            int s = idx >> 6, col = idx & 63;
            int o = o0 + col;
            float v = (s < NSTY && o < NOUT) ? fmaxf(H[(size_t)s * NOUT + o], 0.0f) : 0.0f;
            uint32_t hi = f2tf32(v);
            Hh[s][col] = hi;
            Hl[s][col] = f2tf32(v - __uint_as_float(hi));
        }
        __syncthreads();
        #pragma unroll
        for (int ks = 0; ks < 8; ks++) {
            int kb = ks * 8;
            uint32_t ah[2][4], al[2][4], bh[2][2], bl[2][2];
            #pragma unroll
            for (int mi = 0; mi < 2; mi++) {
                int mr = m0w + mi * 16;
                ah[mi][0] = Hh[mr + r][kb + tg];
                ah[mi][1] = Hh[mr + r + 8][kb + tg];
                ah[mi][2] = Hh[mr + r][kb + tg + 4];
                ah[mi][3] = Hh[mr + r + 8][kb + tg + 4];
                al[mi][0] = Hl[mr + r][kb + tg];
                al[mi][1] = Hl[mr + r + 8][kb + tg];
                al[mi][2] = Hl[mr + r][kb + tg + 4];
                al[mi][3] = Hl[mr + r + 8][kb + tg + 4];
            }
            #pragma unroll
            for (int ni = 0; ni < 2; ni++) {
                int nc = n0w + ni * 8 + r;
                bh[ni][0] = Hh[nc][kb + tg];
                bh[ni][1] = Hh[nc][kb + tg + 4];
                bl[ni][0] = Hl[nc][kb + tg];
                bl[ni][1] = Hl[nc][kb + tg + 4];
            }
            #pragma unroll
            for (int mi = 0; mi < 2; mi++)
                #pragma unroll
                for (int ni = 0; ni < 2; ni++) {
                    mma_tf32(acc[mi][ni], ah[mi], bh[ni]);
                    mma_tf32(acc[mi][ni], ah[mi], bl[ni]);
                    mma_tf32(acc[mi][ni], al[mi], bh[ni]);
                }
        }
        __syncthreads();
    }
    #pragma unroll
    for (int mi = 0; mi < 2; mi++) {
        int s0 = m0w + mi * 16 + r, s1 = s0 + 8;
        #pragma unroll
        for (int ni = 0; ni < 2; ni++) {
            int t0 = n0w + ni * 8 + 2 * tg;
            atomicAdd(&g_K[z][s0 * 64 + t0],     (double)acc[mi][ni][0]);
            atomicAdd(&g_K[z][s0 * 64 + t0 + 1], (double)acc[mi][ni][1]);
            atomicAdd(&g_K[z][s1 * 64 + t0],     (double)acc[mi][ni][2]);
            atomicAdd(&g_K[z][s1 * 64 + t0 + 1], (double)acc[mi][ni][3]);
        }
    }
}

// ---- gram: G = relu(P)^T relu(P), one 128-d chunk ----
__device__ void dev_gram(uint32_t* sm, int d0blk, int z,
                         const float* Pm, const float* Nm) {
    float (*Pc)[68] = (float (*)[68])sm;
    const float* M = z ? Nm : Pm;
    int d0 = d0blk * 128;
    int tid = threadIdx.x;
    int s0 = (tid >> 4) * 4, t0 = (tid & 15) * 4;

    #pragma unroll
    for (int i = 0; i < 32; i++) {
        int idx = tid + i * 256;
        int s = idx & 63, dl = idx >> 6;
        int d = d0 + dl;
        Pc[dl][s] = (s < NSTY && d < D2) ? fmaxf(M[d * NSTY + s], 0.0f) : 0.0f;
    }
    __syncthreads();

    float g[4][4];
    #pragma unroll
    for (int i = 0; i < 4; i++)
        #pragma unroll
        for (int j = 0; j < 4; j++) g[i][j] = 0.0f;
    for (int dl = 0; dl < 128; dl++) {
        float4 a = *(const float4*)&Pc[dl][s0];
        float4 b = *(const float4*)&Pc[dl][t0];
        float av[4] = {a.x, a.y, a.z, a.w};
        float bv[4] = {b.x, b.y, b.z, b.w};
        #pragma unroll
        for (int i = 0; i < 4; i++)
            #pragma unroll
            for (int j = 0; j < 4; j++)
                g[i][j] = fmaf(av[i], bv[j], g[i][j]);
    }
    #pragma unroll
    for (int i = 0; i < 4; i++)
        #pragma unroll
        for (int j = 0; j < 4; j++)
            atomicAdd(&g_G[z][(s0 + i) * 64 + t0 + j], (double)g[i][j]);
}

// ---- cross: C = relu(P)^T m, contract with relu(H); + sum m^2 (R14 body) ----
#define CR_NT 46
__device__ void dev_cross(uint32_t* cs, int ob, int z,
                          const float* Pm, const float* Nm,
                          const float* H1, const float* H2,
                          const float* mpos, const float* mneg) {
    uint32_t (*Ah)[64][20]  = (uint32_t (*)[64][20])cs;
    uint32_t (*Bh)[16][264] = (uint32_t (*)[16][264])(cs + 2 * 64 * 20);

    const float* M  = z ? Nm : Pm;
    const float* H  = z ? H2 : H1;
    const float* mm = z ? mneg : mpos;
    int o0 = ob * 256;
    int tid = threadIdx.x;
    int lane = tid & 31, w = tid >> 5;
    int r = lane >> 2, tg = lane & 3;
    int n0w = w * 32;

    int s_a = tid & 63;
    int k_a = tid >> 6;
    int c2  = (tid & 127) * 2;
    int kb2 = tid >> 7;

    float acc[4][4][4];
    #pragma unroll
    for (int mi = 0; mi < 4; mi++)
        #pragma unroll
        for (int ni = 0; ni < 4; ni++)
            #pragma unroll
            for (int q = 0; q < 4; q++) acc[mi][ni][q] = 0.0f;
    float msq = 0.0f;

    #pragma unroll
    for (int i = 0; i < 4; i++) {
        int kk = k_a + 4 * i;
        float v = (s_a < NSTY) ? fmaxf(M[kk * NSTY + s_a], 0.0f) : 0.0f;
        Ah[0][s_a][kk] = f2tf32(v);
    }
    #pragma unroll
    for (int i = 0; i < 8; i++) {
        int kk = kb2 + 2 * i;
        int o = o0 + c2;
        float2 v = (o < NOUT) ? *(const float2*)&mm[(size_t)kk * NOUT + o]
                              : make_float2(0.0f, 0.0f);
        msq = fmaf(v.x, v.x, msq); msq = fmaf(v.y, v.y, msq);
        Bh[0][kk][c2] = f2tf32(v.x);  Bh[0][kk][c2 + 1] = f2tf32(v.y);
    }
    __syncthreads();

    float  pa[4];
    float2 pm[8];
    for (int t = 0; t < CR_NT; t++) {
        int buf = t & 1;
        if (t + 1 < CR_NT) {
            int k0 = (t + 1) * 16;
            #pragma unroll
            for (int i = 0; i < 4; i++) {
                int d = k0 + k_a + 4 * i;
                pa[i] = (s_a < NSTY && d < D2) ? fmaxf(M[d * NSTY + s_a], 0.0f) : 0.0f;
            }
            #pragma unroll
            for (int i = 0; i < 8; i++) {
                int d = k0 + kb2 + 2 * i;
                int o = o0 + c2;
                pm[i] = (d < D2 && o < NOUT)
                    ? *(const float2*)&mm[(size_t)d * NOUT + o]
                    : make_float2(0.0f, 0.0f);
            }
        }
        #pragma unroll
        for (int ks = 0; ks < 2; ks++) {
            int kb = ks * 8;
            uint32_t af[4][4], bf[4][2];
            #pragma unroll
            for (int mi = 0; mi < 4; mi++) {
                int mr = mi * 16;
                af[mi][0] = Ah[buf][mr + r][kb + tg];
                af[mi][1] = Ah[buf][mr + r + 8][kb + tg];
                af[mi][2] = Ah[buf][mr + r][kb + tg + 4];
                af[mi][3] = Ah[buf][mr + r + 8][kb + tg + 4];
            }
            #pragma unroll
            for (int ni = 0; ni < 4; ni++) {
                int nc = n0w + ni * 8 + r;
                bf[ni][0] = Bh[buf][kb + tg][nc];
                bf[ni][1] = Bh[buf][kb + tg + 4][nc];
            }
            #pragma unroll
            for (int mi = 0; mi < 4; mi++)
                #pragma unroll
                for (int ni = 0; ni < 4; ni++)
                    mma_tf32(acc[mi][ni], af[mi], bf[ni]);
        }
        if (t + 1 < CR_NT) {
            int nb = buf ^ 1;
            #pragma unroll
            for (int i = 0; i < 4; i++)
                Ah[nb][s_a][k_a + 4 * i] = f2tf32(pa[i]);
            #pragma unroll
            for (int i = 0; i < 8; i++) {
                int kk = kb2 + 2 * i;
                msq = fmaf(pm[i].x, pm[i].x, msq);
                msq = fmaf(pm[i].y, pm[i].y, msq);
                Bh[nb][kk][c2] = f2tf32(pm[i].x);  Bh[nb][kk][c2 + 1] = f2tf32(pm[i].y);
            }
        }
        __syncthreads();
    }

    float cr = 0.0f;
    #pragma unroll
    for (int mi = 0; mi < 4; mi++) {
        int s0 = mi * 16 + r, s1 = s0 + 8;
        #pragma unroll
        for (int ni = 0; ni < 4; ni++) {
            int o = o0 + n0w + ni * 8 + 2 * tg;
            if (o < NOUT) {
                if (s0 < NSTY) {
                    float2 h = *(const float2*)&H[(size_t)s0 * NOUT + o];
                    cr = fmaf(acc[mi][ni][0], fmaxf(h.x, 0.0f), cr);
                    cr = fmaf(acc[mi][ni][1], fmaxf(h.y, 0.0f), cr);
                }
                if (s1 < NSTY) {
                    float2 h = *(const float2*)&H[(size_t)s1 * NOUT + o];
                    cr = fmaf(acc[mi][ni][2], fmaxf(h.x, 0.0f), cr);
                    cr = fmaf(acc[mi][ni][3], fmaxf(h.y, 0.0f), cr);
                }
            }
        }
    }
    #pragma unroll
    for (int off = 16; off > 0; off >>= 1) {
        cr  += __shfl_xor_sync(0xffffffffu, cr, off);
        msq += __shfl_xor_sync(0xffffffffu, msq, off);
    }
    __shared__ float rs1[8], rs2[8];
    if (lane == 0) { rs1[w] = cr; rs2[w] = msq; }
    __syncthreads();
    if (tid == 0) {
        float t1 = 0.0f, t2 = 0.0f;
        #pragma unroll
        for (int q = 0; q < 8; q++) { t1 += rs1[q]; t2 += rs2[q]; }
        atomicAdd(&g_acc[2], (double)t1);
        atomicAdd(&g_acc[1], (double)t2);
    }
}

// ---- emb: 64m x 128n tf32 GEMM + bias + sigmoid (R14 body, no (256,3)) ----
#define EBK 16
#define EKT 23
__device__ void dev_emb(uint32_t* sm, int mt, int nt, int z,
                        const float* fi, const float* fj, const float* fk,
                        const float* Wt, const float* bt,
                        const float* Wb, const float* bb) {
    uint32_t (*As)[64][20]  = (uint32_t (*)[64][20])sm;
    uint32_t (*Bs)[EBK][136] = (uint32_t (*)[EBK][136])(sm + 2 * 64 * 20);
    const float* A    = (z == 0) ? fi : (z == 1 ? fj : fk);
    const float* B    = (z == 0) ? Wt : Wb;
    const float* bias = (z == 0) ? bt : bb;
    int m0 = mt * 64;
    int n0 = nt * 128;
    int tid = threadIdx.x;
    int lane = tid & 31, w = tid >> 5;
    int r = lane >> 2, tg = lane & 3;
    int m0w = (w >> 2) * 32;
    int n0w = (w & 3) * 32;

    int lm = tid >> 3;
    int lk = (tid & 7) * 2;
    int ln = tid & 127;
    int lkb = tid >> 7;

    float acc[2][4][4];
    #pragma unroll
    for (int mi = 0; mi < 2; mi++)
        #pragma unroll
        for (int ni = 0; ni < 4; ni++)
            #pragma unroll
            for (int q = 0; q < 4; q++) acc[mi][ni][q] = 0.0f;

    #pragma unroll
    for (int i = 0; i < 2; i++) {
        int m = lm + 32 * i;
        float2 t = *(const float2*)&A[(size_t)(m0 + m) * IN_DIM + lk];
        As[0][m][lk] = f2tf32(t.x); As[0][m][lk + 1] = f2tf32(t.y);
    }
    #pragma unroll
    for (int i = 0; i < 8; i++) {
        int kk = lkb + 2 * i;
        Bs[0][kk][ln] = f2tf32(B[(size_t)kk * HID + n0 + ln]);
    }
    __syncthreads();

    for (int t = 0; t < EKT; t++) {
        int buf = t & 1;
        if (t + 1 < EKT) {
            int k0 = (t + 1) * EBK;
            int nb = buf ^ 1;
            #pragma unroll
            for (int i = 0; i < 2; i++) {
                int m = lm + 32 * i;
                int kg = k0 + lk;
                float v0 = 0.0f, v1 = 0.0f;
                if (kg < IN_DIM) {
                    float2 tv = *(const float2*)&A[(size_t)(m0 + m) * IN_DIM + kg];
                    v0 = tv.x; v1 = tv.y;
                }
                As[nb][m][lk] = f2tf32(v0); As[nb][m][lk + 1] = f2tf32(v1);
            }
            #pragma unroll
            for (int i = 0; i < 8; i++) {
                int kk = lkb + 2 * i;
                int kg = k0 + kk;
                float v = (kg < IN_DIM) ? B[(size_t)kg * HID + n0 + ln] : 0.0f;
                Bs[nb][kk][ln] = f2tf32(v);
            }
        }
        #pragma unroll
        for (int ks = 0; ks < 2; ks++) {
            int kb = ks * 8;
            uint32_t af[2][4], bf[4][2];
            #pragma unroll
            for (int mi = 0; mi < 2; mi++) {
                int mr = m0w + mi * 16;
                af[mi][0] = As[buf][mr + r][kb + tg];
                af[mi][1] = As[buf][mr + r + 8][kb + tg];
                af[mi][2] = As[buf][mr + r][kb + tg + 4];
                af[mi][3] = As[buf][mr + r + 8][kb + tg + 4];
            }
            #pragma unroll
            for (int ni = 0; ni < 4; ni++) {
                int nc = n0w + ni * 8 + r;
                bf[ni][0] = Bs[buf][kb + tg][nc];
                bf[ni][1] = Bs[buf][kb + tg + 4][nc];
            }
            #pragma unroll
            for (int mi = 0; mi < 2; mi++)
                #pragma unroll
                for (int ni = 0; ni < 4; ni++)
                    mma_tf32(acc[mi][ni], af[mi], bf[ni]);
        }
        __syncthreads();
    }

    #pragma unroll
    for (int ni = 0; ni < 4; ni++) {
        int col = n0 + n0w + ni * 8 + 2 * tg;
        float b0 = bias[col], b1 = bias[col + 1];
        #pragma unroll
        for (int mi = 0; mi < 2; mi++) {
            int row0 = m0 + m0w + mi * 16 + r;
            float2 o0v, o1v;
            o0v.x = sigmoid_f(acc[mi][ni][0] + b0);
            o0v.y = sigmoid_f(acc[mi][ni][1] + b1);
            o1v.x = sigmoid_f(acc[mi][ni][2] + b0);
            o1v.y = sigmoid_f(acc[mi][ni][3] + b1);
            *(float2*)&g_emb[z][row0][col]     = o0v;
            *(float2*)&g_emb[z][row0 + 8][col] = o1v;
        }
    }
}

// ================= mega kernel 1: style | hgram | gram | cross | emb =================
#define N_CROSS 390
#define N_EMB   1536
#define N_STYLE 120
#define N_HG    296
#define N_GRAM  12
#define N_MEGA  (N_CROSS + N_EMB + N_STYLE + N_HG + N_GRAM)   // 2354
#define MEGA_SMEM 44032
__global__ __launch_bounds__(256, 2) void k_mega(
        const float* __restrict__ fi, const float* __restrict__ fj,
        const float* __restrict__ fk,
        const float* __restrict__ Wt, const float* __restrict__ bt,
        const float* __restrict__ Wb, const float* __restrict__ bb,
        const float* __restrict__ Pm, const float* __restrict__ Nm,
        const float* __restrict__ H1, const float* __restrict__ H2,
        const float* __restrict__ mpos, const float* __restrict__ mneg) {
    extern __shared__ uint32_t sm[];
    unsigned j = ((unsigned)blockIdx.x * 1237u) % (unsigned)N_MEGA;
    if (j < N_CROSS) {
        dev_cross(sm, j >> 1, j & 1, Pm, Nm, H1, H2, mpos, mneg);
    } else if (j < N_CROSS + N_EMB) {
        unsigned e = j - N_CROSS;
        int z = e % 3;
        unsigned rest = e / 3;
        dev_emb(sm, rest >> 1, rest & 1, z, fi, fj, fk, Wt, bt, Wb, bb);
    } else if (j < N_CROSS + N_EMB + N_STYLE) {
        unsigned sid = j - (N_CROSS + N_EMB);
        dev_style(sm, sid % 60, sid / 60, Pm, Nm, Wt, bt, Wb, bb);
    } else if (j < N_CROSS + N_EMB + N_STYLE + N_HG) {
        unsigned h = j - (N_CROSS + N_EMB + N_STYLE);
        dev_hgram(sm, h % 148, h / 148, H1, H2);
    } else {
        unsigned gd = j - (N_CROSS + N_EMB + N_STYLE + N_HG);
        dev_gram(sm, gd % 6, gd / 6, Pm, Nm);
    }
}

// ================= kernel 2: argmin | pair interleaved =================
// ---- argmin body (R14 128-row version) ----
#define ANT 46
#define AG_AH 0
#define AG_AL (2 * 128 * 20)
#define AG_SH (4 * 128 * 20)
#define AG_SL (4 * 128 * 20 + 2 * 16 * 68)
#define AG_SMEM ((4 * 128 * 20 + 4 * 16 * 68) * 4)   // 58368
__device__ void dev_argmin(uint32_t* sb, int bt_, int z,
                           const float* fi, const float* fj, const float* fk,
                           const float* Pm, const float* Nm) {
    uint32_t (*Ah)[128][20] = (uint32_t (*)[128][20])(sb + AG_AH);
    uint32_t (*Al)[128][20] = (uint32_t (*)[128][20])(sb + AG_AL);
    uint32_t (*Sh)[16][68]  = (uint32_t (*)[16][68])(sb + AG_SH);
    uint32_t (*Sl)[16][68]  = (uint32_t (*)[16][68])(sb + AG_SL);

    const float* fa = fi;
    const float* fb = z ? fk : fj;
    const float* M  = z ? Nm : Pm;
    int b0 = bt_ * 128;
    int tid = threadIdx.x;
    int lane = tid & 31, w = tid >> 5;
    int r = lane >> 2, tg = lane & 3;
    int m0w = (w >> 1) * 32;
    int n0w = (w & 1) * 32;
    int lm = tid >> 3;
    int lk = (tid & 7) * 2;
    int s_s = tid & 63;
    int s_k = tid >> 6;

    float acc[2][4][4];
    #pragma unroll
    for (int mi = 0; mi < 2; mi++)
        #pragma unroll
        for (int ni = 0; ni < 4; ni++)
            #pragma unroll
            for (int q = 0; q < 4; q++) acc[mi][ni][q] = 0.0f;

    #pragma unroll
    for (int i = 0; i < 4; i++) {
        int row = lm + 32 * i;
        float2 t = loadF2(fa, fb, b0 + row, lk);
        uint32_t hx = f2tf32(t.x), hy = f2tf32(t.y);
        Ah[0][row][lk] = hx;  Ah[0][row][lk + 1] = hy;
        Al[0][row][lk]     = f2tf32(t.x - __uint_as_float(hx));
        Al[0][row][lk + 1] = f2tf32(t.y - __uint_as_float(hy));
    }
    #pragma unroll
    for (int i = 0; i < 4; i++) {
        int kk = s_k + 4 * i;
        float v = (s_s < NSTY) ? fmaxf(M[kk * NSTY + s_s], 0.0f) : 0.0f;
        uint32_t hi = f2tf32(v);
        Sh[0][kk][s_s] = hi;
        Sl[0][kk][s_s] = f2tf32(v - __uint_as_float(hi));
    }
    __syncthreads();

    float2 fr[4];
    float  sr[4];
    for (int t = 0; t < ANT; t++) {
        int buf = t & 1;
        if (t + 1 < ANT) {
            int k0 = (t + 1) * 16;
            #pragma unroll
            for (int i = 0; i < 4; i++)
                fr[i] = loadF2(fa, fb, b0 + lm + 32 * i, k0 + lk);
            #pragma unroll
            for (int i = 0; i < 4; i++) {
                int d = k0 + s_k + 4 * i;
                sr[i] = (s_s < NSTY && d < D2) ? fmaxf(M[d * NSTY + s_s], 0.0f) : 0.0f;
            }
        }
        #pragma unroll
        for (int ks = 0; ks < 2; ks++) {
            int kb = ks * 8;
            uint32_t ah[2][4], al[2][4], bh[4][2], bl[4][2];
            #pragma unroll
            for (int mi = 0; mi < 2; mi++) {
                int mr = m0w + mi * 16;
                ah[mi][0] = Ah[buf][mr + r][kb + tg];
                ah[mi][1] = Ah[buf][mr + r + 8][kb + tg];
                ah[mi][2] = Ah[buf][mr + r][kb + tg + 4];
                ah[mi][3] = Ah[buf][mr + r + 8][kb + tg + 4];
                al[mi][0] = Al[buf][mr + r][kb + tg];
                al[mi][1] = Al[buf][mr + r + 8][kb + tg];
                al[mi][2] = Al[buf][mr + r][kb + tg + 4];
                al[mi][3] = Al[buf][mr + r + 8][kb + tg + 4];
            }
            #pragma unroll
            for (int ni = 0; ni < 4; ni++) {
                int nc = n0w + ni * 8 + r;
                bh[ni][0] = Sh[buf][kb + tg][nc];
                bh[ni][1] = Sh[buf][kb + tg + 4][nc];
                bl[ni][0] = Sl[buf][kb + tg][nc];
                bl[ni][1] = Sl[buf][kb + tg + 4][nc];
            }
            #pragma unroll
            for (int mi = 0; mi < 2; mi++)
                #pragma unroll
                for (int ni = 0; ni < 4; ni++) {
                    mma_tf32(acc[mi][ni], ah[mi], bh[ni]);
                    mma_tf32(acc[mi][ni], ah[mi], bl[ni]);
                    mma_tf32(acc[mi][ni], al[mi], bh[ni]);
                }
        }
        if (t + 1 < ANT) {
            int nb = buf ^ 1;
            #pragma unroll
            for (int i = 0; i < 4; i++) {
                int row = lm + 32 * i;
                uint32_t hx = f2tf32(fr[i].x), hy = f2tf32(fr[i].y);
                Ah[nb][row][lk] = hx;  Ah[nb][row][lk + 1] = hy;
                Al[nb][row][lk]     = f2tf32(fr[i].x - __uint_as_float(hx));
                Al[nb][row][lk + 1] = f2tf32(fr[i].y - __uint_as_float(hy));
            }
            #pragma unroll
            for (int i = 0; i < 4; i++) {
                int kk = s_k + 4 * i;
                uint32_t hi = f2tf32(sr[i]);
                Sh[nb][kk][s_s] = hi;
                Sl[nb][kk][s_s] = f2tf32(sr[i] - __uint_as_float(hi));
            }
        }
        __syncthreads();
    }

    float (*Cs)[68] = (float (*)[68])sb;
    #pragma unroll
    for (int mi = 0; mi < 2; mi++) {
        int mr = m0w + mi * 16;
        #pragma unroll
        for (int ni = 0; ni < 4; ni++) {
            int nc = n0w + ni * 8 + 2 * tg;
            Cs[mr + r][nc]         = acc[mi][ni][0];
            Cs[mr + r][nc + 1]     = acc[mi][ni][1];
            Cs[mr + r + 8][nc]     = acc[mi][ni][2];
            Cs[mr + r + 8][nc + 1] = acc[mi][ni][3];
        }
    }
    __syncthreads();
    if (tid < 128) {
        float best = FLT_MAX;
        int bi = 0;
        const float* crow = Cs[tid];
        #pragma unroll
        for (int s = 0; s < NSTY; s++) {
            float v = g_cnorm[z][s] - 2.0f * crow[s];
            if (v < best) { best = v; bi = s; }
        }
        g_idx[z][b0 + tid] = bi;
    }
}

__device__ void dev_pair(int pid) {
    int tid  = threadIdx.x;
    int row  = pid * 8 + (tid >> 5);
    int lane = tid & 31;
    const float4* ti = (const float4*)&g_emb[0][row][0];
    const float4* bj = (const float4*)&g_emb[1][row][0];
    const float4* bk = (const float4*)&g_emb[2][row][0];
    float aij = 0.0f, aik = 0.0f;
    #pragma unroll
    for (int q = 0; q < 2; q++) {
        int c4 = lane + q * 32;
        float4 t = ti[c4], j = bj[c4], k = bk[c4];
        aij += t.x * j.x + t.y * j.y + t.z * j.z + t.w * j.w;
        aik += t.x * k.x + t.y * k.y + t.z * k.z + t.w * k.w;
    }
    for (int off = 16; off > 0; off >>= 1) {
        aij += __shfl_xor_sync(0xffffffffu, aij, off);
        aik += __shfl_xor_sync(0xffffffffu, aik, off);
    }
    __shared__ float s1[8], sa[8];
    if (lane == 0) {
        float x = aij - aik;
        s1[tid >> 5] = softplus_f(-x);
        sa[tid >> 5] = (aij >= aik) ? 1.0f : 0.0f;
    }
    __syncthreads();
    if (tid == 0) {
        float l1 = 0.0f, au = 0.0f;
        #pragma unroll
        for (int q = 0; q < 8; q++) { l1 += s1[q]; au += sa[q]; }
        atomicAdd(&g_acc[0], (double)l1);
        atomicAdd(&g_acc[3], (double)au);
    }
}

// kernel2: 2304 blocks; bid%9==0 -> argmin (256), else pair (2048)
__global__ __launch_bounds__(256) void k_stage2(
        const float* __restrict__ fi, const float* __restrict__ fj,
        const float* __restrict__ fk,
        const float* __restrict__ Pm, const float* __restrict__ Nm) {
    extern __shared__ uint32_t sb[];
    int bid = blockIdx.x;
    if (bid % 9 == 0) {
        int aid = bid / 9;                 // 0..255
        dev_argmin(sb, aid >> 1, aid & 1, fi, fj, fk, Pm, Nm);
    } else {
        int pid = bid - bid / 9 - 1;       // 0..2047
        dev_pair(pid);
    }
}

// ---------------- final ----------------
__global__ void k_final(float* __restrict__ out) {
    __shared__ float s0[NSTY], s1[NSTY];
    __shared__ float red[256];
    __shared__ double redd[256];
    int tid = threadIdx.x;
    if (tid < NSTY) { s0[tid] = g_sscore[0][tid]; s1[tid] = g_sscore[1][tid]; }
    __syncthreads();
    float l = 0.0f;
    for (int b = tid; b < BATCH; b += 256) {
        float x = s0[g_idx[0][b]] - s1[g_idx[1][b]];
        l += softplus_f(-x);
    }
    double gk = 0.0;
    for (int idx = tid; idx < 8192; idx += 256)
        gk += ((const double*)g_G)[idx] * ((const double*)g_K)[idx];
    red[tid] = l; redd[tid] = gk;
    __syncthreads();
    for (int off = 128; off > 0; off >>= 1) {
        if (tid < off) { red[tid] += red[tid + off]; redd[tid] += redd[tid + off]; }
        __syncthreads();
    }
    if (tid == 0) {
        double l1  = g_acc[0] / (double)BATCH;
        double l2  = (double)red[0] / (double)BATCH;
        double l3sum = g_acc[1] - 2.0 * g_acc[2] + redd[0];
        double l3  = l3sum / ((double)D2 * (double)NOUT);
        double auc = g_acc[3] / (double)BATCH;
        out[0] = (float)(l1 + l2 + 0.1 * l3);
        out[1] = (float)l1;
        out[2] = (float)l2;
        out[3] = (float)l3;
        out[4] = (float)auc;
    }
}

// ---------------- launch ----------------
extern "C" void kernel_launch(void* const* d_in, const int* in_sizes, int n_in,
                              void* d_out, int out_size) {
    const float* i_f   = (const float*)d_in[0];
    const float* j_f   = (const float*)d_in[1];
    const float* k_f   = (const float*)d_in[2];
    const float* W_top = (const float*)d_in[3];
    const float* b_top = (const float*)d_in[4];
    const float* W_bot = (const float*)d_in[5];
    const float* b_bot = (const float*)d_in[6];
    const float* P_nmf = (const float*)d_in[7];
    const float* N_nmf = (const float*)d_in[8];
    const float* H1    = (const float*)d_in[9];
    const float* H2    = (const float*)d_in[10];
    const float* mpos  = (const float*)d_in[11];
    const float* mneg  = (const float*)d_in[12];
    float* out = (float*)d_out;

    static bool init_done = false;
    if (!init_done) {
        cudaFuncSetAttribute(k_mega,   cudaFuncAttributeMaxDynamicSharedMemorySize, MEGA_SMEM);
        cudaFuncSetAttribute(k_stage2, cudaFuncAttributeMaxDynamicSharedMemorySize, AG_SMEM);
        init_done = true;
    }

    k_zero<<<64, 256>>>();                                                          // 1
    k_mega<<<N_MEGA, 256, MEGA_SMEM>>>(i_f, j_f, k_f, W_top, b_top, W_bot, b_bot,
                                       P_nmf, N_nmf, H1, H2, mpos, mneg);           // 2
    k_stage2<<<2304, 256, AG_SMEM>>>(i_f, j_f, k_f, P_nmf, N_nmf);                  // 3
    k_final<<<1, 256>>>(out);                                                       // 4
}

// round 17
// speedup vs baseline: 1.0613x; 1.0613x over previous
#include <cuda_runtime.h>
#include <math.h>
#include <float.h>
#include <stdint.h>

#define BATCH   16384
#define IN_DIM  362
#define HID     256
#define NSTY    60
#define NOUT    49710
#define D2      724     // 2*IN_DIM

// ---------------- scratch ----------------
__device__ float  g_emb[3][BATCH][HID];
__device__ int    g_idx[2][BATCH];
__device__ float  g_sscore[2][NSTY];
__device__ float  g_cnorm[2][NSTY];
__device__ double g_acc[5];               // 0:loss1 1:msq 2:cross 3:auc 4:loss2
__device__ double g_K[2][4096];
__device__ double g_G[2][4096];

// ---------------- helpers ----------------
__device__ __forceinline__ float sigmoid_f(float x) { return 1.0f / (1.0f + expf(-x)); }
__device__ __forceinline__ float softplus_f(float y) {
    return fmaxf(y, 0.0f) + log1pf(expf(-fabsf(y)));
}
__device__ __forceinline__ uint32_t f2tf32(float x) {
    uint32_t r;
    asm("cvt.rna.tf32.f32 %0, %1;" : "=r"(r) : "f"(x));
    return r;
}
__device__ __forceinline__ void mma_tf32(float* d, const uint32_t* a, const uint32_t* b) {
    asm volatile(
        "mma.sync.aligned.m16n8k8.row.col.f32.tf32.tf32.f32 "
        "{%0,%1,%2,%3}, {%4,%5,%6,%7}, {%8,%9}, {%0,%1,%2,%3};"
        : "+f"(d[0]), "+f"(d[1]), "+f"(d[2]), "+f"(d[3])
        : "r"(a[0]), "r"(a[1]), "r"(a[2]), "r"(a[3]), "r"(b[0]), "r"(b[1]));
}
__device__ __forceinline__ float2 loadF2(const float* fa, const float* fb,
                                         int rowg, int d) {
    if (d < IN_DIM) return *(const float2*)&fa[(size_t)rowg * IN_DIM + d];
    if (d < D2)     return *(const float2*)&fb[(size_t)rowg * IN_DIM + d - IN_DIM];
    return make_float2(0.0f, 0.0f);
}

// ---------------- K0: zero ----------------
__global__ void k_zero() {
    int gid = blockIdx.x * 256 + threadIdx.x;
    if (gid < 8192)      ((double*)g_K)[gid] = 0.0;
    else                 ((double*)g_G)[gid - 8192] = 0.0;
    if (gid < 5) g_acc[gid] = 0.0;
}

// ---------------- K1: per-style score table + column norms ----------------
__global__ void k_style(const float* __restrict__ Pm, const float* __restrict__ Nm,
                        const float* __restrict__ Wt, const float* __restrict__ bt,
                        const float* __restrict__ Wb, const float* __restrict__ bb) {
    __shared__ float pc[D2];
    __shared__ float red[256];
    int s = blockIdx.x;
    int z = blockIdx.y;
    const float* M = z ? Nm : Pm;
    for (int d = threadIdx.x; d < D2; d += 256)
        pc[d] = fmaxf(M[d * NSTY + s], 0.0f);
    __syncthreads();

    int h = threadIdx.x;
    float t = bt[h], b = bb[h];
    for (int d = 0; d < IN_DIM; d++) {
        t = fmaf(pc[d],          Wt[d * HID + h], t);
        b = fmaf(pc[IN_DIM + d], Wb[d * HID + h], b);
    }
    float v = sigmoid_f(t) * sigmoid_f(b);
    red[h] = v; __syncthreads();
    for (int off = 128; off > 0; off >>= 1) {
        if (h < off) red[h] += red[h + off];
        __syncthreads();
    }
    if (h == 0) g_sscore[z][s] = red[0];

    float n = 0.0f;
    for (int d = h; d < D2; d += 256) n = fmaf(pc[d], pc[d], n);
    __syncthreads();
    red[h] = n; __syncthreads();
    for (int off = 128; off > 0; off >>= 1) {
        if (h < off) red[h] += red[h + off];
        __syncthreads();
    }
    if (h == 0) g_cnorm[z][s] = red[0];
}

// ---------------- K2: argmin via split-tf32 MMA (R14/128-row) ----------------
#define ANT 46
#define AG_AH 0
#define AG_AL (2 * 128 * 20)
#define AG_SH (4 * 128 * 20)
#define AG_SL (4 * 128 * 20 + 2 * 16 * 68)
#define AG_WORDS (4 * 128 * 20 + 4 * 16 * 68)
#define AG_SMEM (AG_WORDS * 4)
__global__ __launch_bounds__(256) void k_argmin_tc(
        const float* __restrict__ fi, const float* __restrict__ fj,
        const float* __restrict__ fk,
        const float* __restrict__ Pm, const float* __restrict__ Nm) {
    extern __shared__ uint32_t sb[];
    uint32_t (*Ah)[128][20] = (uint32_t (*)[128][20])(sb + AG_AH);
    uint32_t (*Al)[128][20] = (uint32_t (*)[128][20])(sb + AG_AL);
    uint32_t (*Sh)[16][68]  = (uint32_t (*)[16][68])(sb + AG_SH);
    uint32_t (*Sl)[16][68]  = (uint32_t (*)[16][68])(sb + AG_SL);

    int z = blockIdx.y;
    const float* fa = fi;
    const float* fb = z ? fk : fj;
    const float* M  = z ? Nm : Pm;
    int b0 = blockIdx.x * 128;
    int tid = threadIdx.x;
    int lane = tid & 31, w = tid >> 5;
    int r = lane >> 2, tg = lane & 3;
    int m0w = (w >> 1) * 32;
    int n0w = (w & 1) * 32;
    int lm = tid >> 3;
    int lk = (tid & 7) * 2;
    int s_s = tid & 63;
    int s_k = tid >> 6;

    float acc[2][4][4];
    #pragma unroll
    for (int mi = 0; mi < 2; mi++)
        #pragma unroll
        for (int ni = 0; ni < 4; ni++)
            #pragma unroll
            for (int q = 0; q < 4; q++) acc[mi][ni][q] = 0.0f;

    #pragma unroll
    for (int i = 0; i < 4; i++) {
        int row = lm + 32 * i;
        float2 t = loadF2(fa, fb, b0 + row, lk);
        uint32_t hx = f2tf32(t.x), hy = f2tf32(t.y);
        Ah[0][row][lk] = hx;  Ah[0][row][lk + 1] = hy;
        Al[0][row][lk]     = f2tf32(t.x - __uint_as_float(hx));
        Al[0][row][lk + 1] = f2tf32(t.y - __uint_as_float(hy));
    }
    #pragma unroll
    for (int i = 0; i < 4; i++) {
        int kk = s_k + 4 * i;
        float v = (s_s < NSTY) ? fmaxf(M[kk * NSTY + s_s], 0.0f) : 0.0f;
        uint32_t hi = f2tf32(v);
        Sh[0][kk][s_s] = hi;
        Sl[0][kk][s_s] = f2tf32(v - __uint_as_float(hi));
    }
    __syncthreads();

    float2 fr[4];
    float  sr[4];
    for (int t = 0; t < ANT; t++) {
        int buf = t & 1;
        if (t + 1 < ANT) {
            int k0 = (t + 1) * 16;
            #pragma unroll
            for (int i = 0; i < 4; i++)
                fr[i] = loadF2(fa, fb, b0 + lm + 32 * i, k0 + lk);
            #pragma unroll
            for (int i = 0; i < 4; i++) {
                int d = k0 + s_k + 4 * i;
                sr[i] = (s_s < NSTY && d < D2) ? fmaxf(M[d * NSTY + s_s], 0.0f) : 0.0f;
            }
        }
        #pragma unroll
        for (int ks = 0; ks < 2; ks++) {
            int kb = ks * 8;
            uint32_t ah[2][4], al[2][4], bh[4][2], bl[4][2];
            #pragma unroll
            for (int mi = 0; mi < 2; mi++) {
                int mr = m0w + mi * 16;
                ah[mi][0] = Ah[buf][mr + r][kb + tg];
                ah[mi][1] = Ah[buf][mr + r + 8][kb + tg];
                ah[mi][2] = Ah[buf][mr + r][kb + tg + 4];
                ah[mi][3] = Ah[buf][mr + r + 8][kb + tg + 4];
                al[mi][0] = Al[buf][mr + r][kb + tg];
                al[mi][1] = Al[buf][mr + r + 8][kb + tg];
                al[mi][2] = Al[buf][mr + r][kb + tg + 4];
                al[mi][3] = Al[buf][mr + r + 8][kb + tg + 4];
            }
            #pragma unroll
            for (int ni = 0; ni < 4; ni++) {
                int nc = n0w + ni * 8 + r;
                bh[ni][0] = Sh[buf][kb + tg][nc];
                bh[ni][1] = Sh[buf][kb + tg + 4][nc];
                bl[ni][0] = Sl[buf][kb + tg][nc];
                bl[ni][1] = Sl[buf][kb + tg + 4][nc];
            }
            #pragma unroll
            for (int mi = 0; mi < 2; mi++)
                #pragma unroll
                for (int ni = 0; ni < 4; ni++) {
                    mma_tf32(acc[mi][ni], ah[mi], bh[ni]);
                    mma_tf32(acc[mi][ni], ah[mi], bl[ni]);
                    mma_tf32(acc[mi][ni], al[mi], bh[ni]);
                }
        }
        if (t + 1 < ANT) {
            int nb = buf ^ 1;
            #pragma unroll
            for (int i = 0; i < 4; i++) {
                int row = lm + 32 * i;
                uint32_t hx = f2tf32(fr[i].x), hy = f2tf32(fr[i].y);
                Ah[nb][row][lk] = hx;  Ah[nb][row][lk + 1] = hy;
                Al[nb][row][lk]     = f2tf32(fr[i].x - __uint_as_float(hx));
                Al[nb][row][lk + 1] = f2tf32(fr[i].y - __uint_as_float(hy));
            }
            #pragma unroll
            for (int i = 0; i < 4; i++) {
                int kk = s_k + 4 * i;
                uint32_t hi = f2tf32(sr[i]);
                Sh[nb][kk][s_s] = hi;
                Sl[nb][kk][s_s] = f2tf32(sr[i] - __uint_as_float(hi));
            }
        }
        __syncthreads();
    }

    float (*Cs)[68] = (float (*)[68])sb;
    #pragma unroll
    for (int mi = 0; mi < 2; mi++) {
        int mr = m0w + mi * 16;
        #pragma unroll
        for (int ni = 0; ni < 4; ni++) {
            int nc = n0w + ni * 8 + 2 * tg;
            Cs[mr + r][nc]         = acc[mi][ni][0];
            Cs[mr + r][nc + 1]     = acc[mi][ni][1];
            Cs[mr + r + 8][nc]     = acc[mi][ni][2];
            Cs[mr + r + 8][nc + 1] = acc[mi][ni][3];
        }
    }
    __syncthreads();
    if (tid < 128) {
        float best = FLT_MAX;
        int bi = 0;
        const float* crow = Cs[tid];
        #pragma unroll
        for (int s = 0; s < NSTY; s++) {
            float v = g_cnorm[z][s] - 2.0f * crow[s];
            if (v < best) { best = v; bi = s; }
        }
        g_idx[z][b0 + tid] = bi;
    }
}

// ---------------- K3: cross term + sum m^2 (R14: plain tf32 m, 2 blocks/SM) ----------------
#define CR_NT 46
#define CR_AH 0
#define CR_BH (2 * 64 * 20)
#define CR_WORDS (2 * 64 * 20 + 2 * 16 * 264)
#define CR_SMEM (CR_WORDS * 4)
__global__ __launch_bounds__(256, 2) void k_cross(
        const float* __restrict__ Pm, const float* __restrict__ Nm,
        const float* __restrict__ H1, const float* __restrict__ H2,
        const float* __restrict__ mpos, const float* __restrict__ mneg) {
    extern __shared__ uint32_t cs[];
    uint32_t (*Ah)[64][20]  = (uint32_t (*)[64][20])(cs + CR_AH);
    uint32_t (*Bh)[16][264] = (uint32_t (*)[16][264])(cs + CR_BH);

    int z = blockIdx.y;
    const float* M  = z ? Nm : Pm;
    const float* H  = z ? H2 : H1;
    const float* mm = z ? mneg : mpos;
    int o0 = blockIdx.x * 256;
    int tid = threadIdx.x;
    int lane = tid & 31, w = tid >> 5;
    int r = lane >> 2, tg = lane & 3;
    int n0w = w * 32;

    int s_a = tid & 63;
    int k_a = tid >> 6;
    int c2  = (tid & 127) * 2;
    int kb2 = tid >> 7;

    float acc[4][4][4];
    #pragma unroll
    for (int mi = 0; mi < 4; mi++)
        #pragma unroll
        for (int ni = 0; ni < 4; ni++)
            #pragma unroll
            for (int q = 0; q < 4; q++) acc[mi][ni][q] = 0.0f;
    float msq = 0.0f;

    #pragma unroll
    for (int i = 0; i < 4; i++) {
        int kk = k_a + 4 * i;
        float v = (s_a < NSTY) ? fmaxf(M[kk * NSTY + s_a], 0.0f) : 0.0f;
        Ah[0][s_a][kk] = f2tf32(v);
    }
    #pragma unroll
    for (int i = 0; i < 8; i++) {
        int kk = kb2 + 2 * i;
        int o = o0 + c2;
        float2 v = (o < NOUT) ? *(const float2*)&mm[(size_t)kk * NOUT + o]
                              : make_float2(0.0f, 0.0f);
        msq = fmaf(v.x, v.x, msq); msq = fmaf(v.y, v.y, msq);
        Bh[0][kk][c2] = f2tf32(v.x);  Bh[0][kk][c2 + 1] = f2tf32(v.y);
    }
    __syncthreads();

    float  pa[4];
    float2 pm[8];
    for (int t = 0; t < CR_NT; t++) {
        int buf = t & 1;
        if (t + 1 < CR_NT) {
            int k0 = (t + 1) * 16;
            #pragma unroll
            for (int i = 0; i < 4; i++) {
                int d = k0 + k_a + 4 * i;
                pa[i] = (s_a < NSTY && d < D2) ? fmaxf(M[d * NSTY + s_a], 0.0f) : 0.0f;
            }
            #pragma unroll
            for (int i = 0; i < 8; i++) {
                int d = k0 + kb2 + 2 * i;
                int o = o0 + c2;
                pm[i] = (d < D2 && o < NOUT)
                    ? *(const float2*)&mm[(size_t)d * NOUT + o]
                    : make_float2(0.0f, 0.0f);
            }
        }
        #pragma unroll
        for (int ks = 0; ks < 2; ks++) {
            int kb = ks * 8;
            uint32_t af[4][4], bf[4][2];
            #pragma unroll
            for (int mi = 0; mi < 4; mi++) {
                int mr = mi * 16;
                af[mi][0] = Ah[buf][mr + r][kb + tg];
                af[mi][1] = Ah[buf][mr + r + 8][kb + tg];
                af[mi][2] = Ah[buf][mr + r][kb + tg + 4];
                af[mi][3] = Ah[buf][mr + r + 8][kb + tg + 4];
            }
            #pragma unroll
            for (int ni = 0; ni < 4; ni++) {
                int nc = n0w + ni * 8 + r;
                bf[ni][0] = Bh[buf][kb + tg][nc];
                bf[ni][1] = Bh[buf][kb + tg + 4][nc];
            }
            #pragma unroll
            for (int mi = 0; mi < 4; mi++)
                #pragma unroll
                for (int ni = 0; ni < 4; ni++)
                    mma_tf32(acc[mi][ni], af[mi], bf[ni]);
        }
        if (t + 1 < CR_NT) {
            int nb = buf ^ 1;
            #pragma unroll
            for (int i = 0; i < 4; i++)
                Ah[nb][s_a][k_a + 4 * i] = f2tf32(pa[i]);
            #pragma unroll
            for (int i = 0; i < 8; i++) {
                int kk = kb2 + 2 * i;
                msq = fmaf(pm[i].x, pm[i].x, msq);
                msq = fmaf(pm[i].y, pm[i].y, msq);
                Bh[nb][kk][c2] = f2tf32(pm[i].x);  Bh[nb][kk][c2 + 1] = f2tf32(pm[i].y);
            }
        }
        __syncthreads();
    }

    float cr = 0.0f;
    #pragma unroll
    for (int mi = 0; mi < 4; mi++) {
        int s0 = mi * 16 + r, s1 = s0 + 8;
        #pragma unroll
        for (int ni = 0; ni < 4; ni++) {
            int o = o0 + n0w + ni * 8 + 2 * tg;
            if (o < NOUT) {
                if (s0 < NSTY) {
                    float2 h = *(const float2*)&H[(size_t)s0 * NOUT + o];
                    cr = fmaf(acc[mi][ni][0], fmaxf(h.x, 0.0f), cr);
                    cr = fmaf(acc[mi][ni][1], fmaxf(h.y, 0.0f), cr);
                }
                if (s1 < NSTY) {
                    float2 h = *(const float2*)&H[(size_t)s1 * NOUT + o];
                    cr = fmaf(acc[mi][ni][2], fmaxf(h.x, 0.0f), cr);
                    cr = fmaf(acc[mi][ni][3], fmaxf(h.y, 0.0f), cr);
                }
            }
        }
    }
    #pragma unroll
    for (int off = 16; off > 0; off >>= 1) {
        cr  += __shfl_xor_sync(0xffffffffu, cr, off);
        msq += __shfl_xor_sync(0xffffffffu, msq, off);
    }
    __shared__ float rs1[8], rs2[8];
    if (lane == 0) { rs1[w] = cr; rs2[w] = msq; }
    __syncthreads();
    if (tid == 0) {
        float t1 = 0.0f, t2 = 0.0f;
        #pragma unroll
        for (int q = 0; q < 8; q++) { t1 += rs1[q]; t2 += rs2[q]; }
        atomicAdd(&g_acc[2], (double)t1);
        atomicAdd(&g_acc[1], (double)t2);
    }
}

// ---------------- K4: K = relu(H) relu(H)^T ----------------
#define HG_CHUNKS 777
#define HG_BLOCKS 148
__global__ __launch_bounds__(256) void k_hgram_tc(
        const float* __restrict__ H1, const float* __restrict__ H2) {
    __shared__ uint32_t Hh[64][68];
    __shared__ uint32_t Hl[64][68];
    int z = blockIdx.y;
    const float* H = z ? H2 : H1;
    int tid = threadIdx.x;
    int lane = tid & 31, w = tid >> 5;
    int r = lane >> 2, tg = lane & 3;
    int m0w = (w >> 2) * 32;
    int n0w = (w & 3) * 16;

    float acc[2][2][4];
    #pragma unroll
    for (int mi = 0; mi < 2; mi++)
        #pragma unroll
        for (int ni = 0; ni < 2; ni++)
            #pragma unroll
            for (int q = 0; q < 4; q++) acc[mi][ni][q] = 0.0f;

    for (int c = blockIdx.x; c < HG_CHUNKS; c += HG_BLOCKS) {
        int o0 = c * 64;
        #pragma unroll
        for (int i = 0; i < 16; i++) {
            int idx = tid + i * 256;
            int s = idx >> 6, col = idx & 63;
            int o = o0 + col;
            float v = (s < NSTY && o < NOUT) ? fmaxf(H[(size_t)s * NOUT + o], 0.0f) : 0.0f;
            uint32_t hi = f2tf32(v);
            Hh[s][col] = hi;
            Hl[s][col] = f2tf32(v - __uint_as_float(hi));
        }
        __syncthreads();
        #pragma unroll
        for (int ks = 0; ks < 8; ks++) {
            int kb = ks * 8;
            uint32_t ah[2][4], al[2][4], bh[2][2], bl[2][2];
            #pragma unroll
            for (int mi = 0; mi < 2; mi++) {
                int mr = m0w + mi * 16;
                ah[mi][0] = Hh[mr + r][kb + tg];
                ah[mi][1] = Hh[mr + r + 8][kb + tg];
                ah[mi][2] = Hh[mr + r][kb + tg + 4];
                ah[mi][3] = Hh[mr + r + 8][kb + tg + 4];
                al[mi][0] = Hl[mr + r][kb + tg];
                al[mi][1] = Hl[mr + r + 8][kb + tg];
                al[mi][2] = Hl[mr + r][kb + tg + 4];
                al[mi][3] = Hl[mr + r + 8][kb + tg + 4];
            }
            #pragma unroll
            for (int ni = 0; ni < 2; ni++) {
                int nc = n0w + ni * 8 + r;
                bh[ni][0] = Hh[nc][kb + tg];
                bh[ni][1] = Hh[nc][kb + tg + 4];
                bl[ni][0] = Hl[nc][kb + tg];
                bl[ni][1] = Hl[nc][kb + tg + 4];
            }
            #pragma unroll
            for (int mi = 0; mi < 2; mi++)
                #pragma unroll
                for (int ni = 0; ni < 2; ni++) {
                    mma_tf32(acc[mi][ni], ah[mi], bh[ni]);
                    mma_tf32(acc[mi][ni], ah[mi], bl[ni]);
                    mma_tf32(acc[mi][ni], al[mi], bh[ni]);
                }
        }
        __syncthreads();
    }
    #pragma unroll
    for (int mi = 0; mi < 2; mi++) {
        int s0 = m0w + mi * 16 + r, s1 = s0 + 8;
        #pragma unroll
        for (int ni = 0; ni < 2; ni++) {
            int t0 = n0w + ni * 8 + 2 * tg;
            atomicAdd(&g_K[z][s0 * 64 + t0],     (double)acc[mi][ni][0]);
            atomicAdd(&g_K[z][s0 * 64 + t0 + 1], (double)acc[mi][ni][1]);
            atomicAdd(&g_K[z][s1 * 64 + t0],     (double)acc[mi][ni][2]);
            atomicAdd(&g_K[z][s1 * 64 + t0 + 1], (double)acc[mi][ni][3]);
        }
    }
}

// ---------------- K5: G = relu(P)^T relu(P) ----------------
__global__ __launch_bounds__(256) void k_gram(
        const float* __restrict__ Pm, const float* __restrict__ Nm) {
    __shared__ float Pc[128][68];
    int z = blockIdx.y;
    const float* M = z ? Nm : Pm;
    int d0 = blockIdx.x * 128;
    int tid = threadIdx.x;
    int s0 = (tid >> 4) * 4, t0 = (tid & 15) * 4;

    #pragma unroll
    for (int i = 0; i < 32; i++) {
        int idx = tid + i * 256;
        int s = idx & 63, dl = idx >> 6;
        int d = d0 + dl;
        Pc[dl][s] = (s < NSTY && d < D2) ? fmaxf(M[d * NSTY + s], 0.0f) : 0.0f;
    }
    __syncthreads();

    float g[4][4];
    #pragma unroll
    for (int i = 0; i < 4; i++)
        #pragma unroll
        for (int j = 0; j < 4; j++) g[i][j] = 0.0f;
    for (int dl = 0; dl < 128; dl++) {
        float4 a = *(const float4*)&Pc[dl][s0];
        float4 b = *(const float4*)&Pc[dl][t0];
        float av[4] = {a.x, a.y, a.z, a.w};
        float bv[4] = {b.x, b.y, b.z, b.w};
        #pragma unroll
        for (int i = 0; i < 4; i++)
            #pragma unroll
            for (int j = 0; j < 4; j++)
                g[i][j] = fmaf(av[i], bv[j], g[i][j]);
    }
    #pragma unroll
    for (int i = 0; i < 4; i++)
        #pragma unroll
        for (int j = 0; j < 4; j++)
            atomicAdd(&g_G[z][(s0 + i) * 64 + t0 + j], (double)g[i][j]);
}

// ---------------- K6: embedding GEMM, 64m x 128n tile ----------------
#define EBK 16
#define EKT 23
__global__ __launch_bounds__(256) void k_emb_tc(
        const float* __restrict__ fi, const float* __restrict__ fj,
        const float* __restrict__ fk,
        const float* __restrict__ Wt, const float* __restrict__ bt,
        const float* __restrict__ Wb, const float* __restrict__ bb) {
    __shared__ uint32_t As[2][64][20];
    __shared__ uint32_t Bs[2][EBK][136];
    int z = blockIdx.z;
    const float* A    = (z == 0) ? fi : (z == 1 ? fj : fk);
    const float* B    = (z == 0) ? Wt : Wb;
    const float* bias = (z == 0) ? bt : bb;
    int m0 = blockIdx.y * 64;
    int n0 = blockIdx.x * 128;
    int tid = threadIdx.x;
    int lane = tid & 31, w = tid >> 5;
    int r = lane >> 2, tg = lane & 3;
    int m0w = (w >> 2) * 32;
    int n0w = (w & 3) * 32;

    int lm = tid >> 3;
    int lk = (tid & 7) * 2;
    int ln = tid & 127;
    int lkb = tid >> 7;

    float acc[2][4][4];
    #pragma unroll
    for (int mi = 0; mi < 2; mi++)
        #pragma unroll
        for (int ni = 0; ni < 4; ni++)
            #pragma unroll
            for (int q = 0; q < 4; q++) acc[mi][ni][q] = 0.0f;

    #pragma unroll
    for (int i = 0; i < 2; i++) {
        int m = lm + 32 * i;
        float2 t = *(const float2*)&A[(size_t)(m0 + m) * IN_DIM + lk];
        As[0][m][lk] = f2tf32(t.x); As[0][m][lk + 1] = f2tf32(t.y);
    }
    #pragma unroll
    for (int i = 0; i < 8; i++) {
        int kk = lkb + 2 * i;
        Bs[0][kk][ln] = f2tf32(B[(size_t)kk * HID + n0 + ln]);
    }
    __syncthreads();

    for (int t = 0; t < EKT; t++) {
        int buf = t & 1;
        if (t + 1 < EKT) {
            int k0 = (t + 1) * EBK;
            int nb = buf ^ 1;
            #pragma unroll
            for (int i = 0; i < 2; i++) {
                int m = lm + 32 * i;
                int kg = k0 + lk;
                float v0 = 0.0f, v1 = 0.0f;
                if (kg < IN_DIM) {
                    float2 tv = *(const float2*)&A[(size_t)(m0 + m) * IN_DIM + kg];
                    v0 = tv.x; v1 = tv.y;
                }
                As[nb][m][lk] = f2tf32(v0); As[nb][m][lk + 1] = f2tf32(v1);
            }
            #pragma unroll
            for (int i = 0; i < 8; i++) {
                int kk = lkb + 2 * i;
                int kg = k0 + kk;
                float v = (kg < IN_DIM) ? B[(size_t)kg * HID + n0 + ln] : 0.0f;
                Bs[nb][kk][ln] = f2tf32(v);
            }
        }
        #pragma unroll
        for (int ks = 0; ks < 2; ks++) {
            int kb = ks * 8;
            uint32_t af[2][4], bf[4][2];
            #pragma unroll
            for (int mi = 0; mi < 2; mi++) {
                int mr = m0w + mi * 16;
                af[mi][0] = As[buf][mr + r][kb + tg];
                af[mi][1] = As[buf][mr + r + 8][kb + tg];
                af[mi][2] = As[buf][mr + r][kb + tg + 4];
                af[mi][3] = As[buf][mr + r + 8][kb + tg + 4];
            }
            #pragma unroll
            for (int ni = 0; ni < 4; ni++) {
                int nc = n0w + ni * 8 + r;
                bf[ni][0] = Bs[buf][kb + tg][nc];
                bf[ni][1] = Bs[buf][kb + tg + 4][nc];
            }
            #pragma unroll
            for (int mi = 0; mi < 2; mi++)
                #pragma unroll
                for (int ni = 0; ni < 4; ni++)
                    mma_tf32(acc[mi][ni], af[mi], bf[ni]);
        }
        __syncthreads();
    }

    #pragma unroll
    for (int ni = 0; ni < 4; ni++) {
        int col = n0 + n0w + ni * 8 + 2 * tg;
        float b0 = bias[col], b1 = bias[col + 1];
        #pragma unroll
        for (int mi = 0; mi < 2; mi++) {
            int row0 = m0 + m0w + mi * 16 + r;
            float2 o0v, o1v;
            o0v.x = sigmoid_f(acc[mi][ni][0] + b0);
            o0v.y = sigmoid_f(acc[mi][ni][1] + b1);
            o1v.x = sigmoid_f(acc[mi][ni][2] + b0);
            o1v.y = sigmoid_f(acc[mi][ni][3] + b1);
            *(float2*)&g_emb[z][row0][col]     = o0v;
            *(float2*)&g_emb[z][row0 + 8][col] = o1v;
        }
    }
}

// ---------------- K7: row dot products -> loss1 + auc ----------------
__global__ void k_pair() {
    int tid  = threadIdx.x;
    int row  = blockIdx.x * 8 + (tid >> 5);
    int lane = tid & 31;
    const float4* ti = (const float4*)&g_emb[0][row][0];
    const float4* bj = (const float4*)&g_emb[1][row][0];
    const float4* bk = (const float4*)&g_emb[2][row][0];
    float aij = 0.0f, aik = 0.0f;
    #pragma unroll
    for (int q = 0; q < 2; q++) {
        int c4 = lane + q * 32;
        float4 t = ti[c4], j = bj[c4], k = bk[c4];
        aij += t.x * j.x + t.y * j.y + t.z * j.z + t.w * j.w;
        aik += t.x * k.x + t.y * k.y + t.z * k.z + t.w * k.w;
    }
    for (int off = 16; off > 0; off >>= 1) {
        aij += __shfl_xor_sync(0xffffffffu, aij, off);
        aik += __shfl_xor_sync(0xffffffffu, aik, off);
    }
    __shared__ float s1[8], sa[8];
    if (lane == 0) {
        float x = aij - aik;
        s1[tid >> 5] = softplus_f(-x);
        sa[tid >> 5] = (aij >= aik) ? 1.0f : 0.0f;
    }
    __syncthreads();
    if (tid == 0) {
        float l1 = 0.0f, au = 0.0f;
        #pragma unroll
        for (int q = 0; q < 8; q++) { l1 += s1[q]; au += sa[q]; }
        atomicAdd(&g_acc[0], (double)l1);
        atomicAdd(&g_acc[3], (double)au);
    }
}

// ---------------- K8: loss2 (parallel, one element per thread) ----------------
__global__ void k_loss2() {
    __shared__ float s0[NSTY], s1[NSTY];
    int tid = threadIdx.x;
    if (tid < NSTY) { s0[tid] = g_sscore[0][tid]; s1[tid] = g_sscore[1][tid]; }
    __syncthreads();
    int b = blockIdx.x * 256 + tid;
    float x = s0[g_idx[0][b]] - s1[g_idx[1][b]];
    float l = softplus_f(-x);
    for (int off = 16; off > 0; off >>= 1)
        l += __shfl_xor_sync(0xffffffffu, l, off);
    __shared__ float rs[8];
    if ((tid & 31) == 0) rs[tid >> 5] = l;
    __syncthreads();
    if (tid == 0) {
        float t = 0.0f;
        #pragma unroll
        for (int q = 0; q < 8; q++) t += rs[q];
        atomicAdd(&g_acc[4], (double)t);
    }
}

// ---------------- K9: finalize (G.K dot + combine) ----------------
__global__ void k_final(float* __restrict__ out) {
    __shared__ double redd[256];
    int tid = threadIdx.x;
    double gk = 0.0;
    for (int idx = tid; idx < 8192; idx += 256)
        gk += ((const double*)g_G)[idx] * ((const double*)g_K)[idx];
    redd[tid] = gk;
    __syncthreads();
    for (int off = 128; off > 0; off >>= 1) {
        if (tid < off) redd[tid] += redd[tid + off];
        __syncthreads();
    }
    if (tid == 0) {
        double l1  = g_acc[0] / (double)BATCH;
        double l2  = g_acc[4] / (double)BATCH;
        double l3sum = g_acc[1] - 2.0 * g_acc[2] + redd[0];
        double l3  = l3sum / ((double)D2 * (double)NOUT);
        double auc = g_acc[3] / (double)BATCH;
        out[0] = (float)(l1 + l2 + 0.1 * l3);
        out[1] = (float)l1;
        out[2] = (float)l2;
        out[3] = (float)l3;
        out[4] = (float)auc;
    }
}

// ---------------- launch (dual-stream fork-join) ----------------
extern "C" void kernel_launch(void* const* d_in, const int* in_sizes, int n_in,
                              void* d_out, int out_size) {
    const float* i_f   = (const float*)d_in[0];
    const float* j_f   = (const float*)d_in[1];
    const float* k_f   = (const float*)d_in[2];
    const float* W_top = (const float*)d_in[3];
    const float* b_top = (const float*)d_in[4];
    const float* W_bot = (const float*)d_in[5];
    const float* b_bot = (const float*)d_in[6];
    const float* P_nmf = (const float*)d_in[7];
    const float* N_nmf = (const float*)d_in[8];
    const float* H1    = (const float*)d_in[9];
    const float* H2    = (const float*)d_in[10];
    const float* mpos  = (const float*)d_in[11];
    const float* mneg  = (const float*)d_in[12];
    float* out = (float*)d_out;

    static cudaStream_t s2 = nullptr;
    static cudaEvent_t  eFork = nullptr, eJoin = nullptr;
    static bool init_done = false;
    if (!init_done) {
        cudaFuncSetAttribute(k_argmin_tc, cudaFuncAttributeMaxDynamicSharedMemorySize, AG_SMEM);
        cudaFuncSetAttribute(k_cross, cudaFuncAttributeMaxDynamicSharedMemorySize, CR_SMEM);
        cudaStreamCreateWithFlags(&s2, cudaStreamNonBlocking);
        cudaEventCreateWithFlags(&eFork, cudaEventDisableTiming);
        cudaEventCreateWithFlags(&eJoin, cudaEventDisableTiming);
        init_done = true;
    }

    // main stream prologue
    k_zero<<<64, 256>>>();                                                          // 1
    k_style<<<dim3(NSTY, 2), 256>>>(P_nmf, N_nmf, W_top, b_top, W_bot, b_bot);      // 2

    cudaEventRecord(eFork, 0);
    cudaStreamWaitEvent(s2, eFork, 0);

    // main stream: loss3 decomposition
    k_hgram_tc<<<dim3(HG_BLOCKS, 2), 256>>>(H1, H2);                                // 3
    k_cross<<<dim3((NOUT + 255) / 256, 2), 256, CR_SMEM>>>(
        P_nmf, N_nmf, H1, H2, mpos, mneg);                                          // 4
    k_gram<<<dim3(6, 2), 256>>>(P_nmf, N_nmf);                                      // 5

    // side stream: emb -> argmin -> pair -> loss2 (loss2 hides under cross)
    k_emb_tc<<<dim3(2, BATCH / 64, 3), 256, 0, s2>>>(i_f, j_f, k_f, W_top, b_top,
                                                     W_bot, b_bot);                 // 6
    k_argmin_tc<<<dim3(BATCH / 128, 2), 256, AG_SMEM, s2>>>(i_f, j_f, k_f,
                                                            P_nmf, N_nmf);          // 7
    k_pair<<<BATCH / 8, 256, 0, s2>>>();                                            // 8
    k_loss2<<<BATCH / 256, 256, 0, s2>>>();                                         // 9
    cudaEventRecord(eJoin, s2);

    cudaStreamWaitEvent(0, eJoin, 0);
    k_final<<<1, 256>>>(out);                                                       // 10
}